// round 4
// baseline (speedup 1.0000x reference)
#include <cuda_runtime.h>

// ---------------------------------------------------------------------------
// TrackCrop: input [32, 512, 512, 3] f32.
// reduce: nonzero count + x/y weighted sums per batch -> centroid -> crop
// origin (published in g_HW, scratch self-resetting for graph replay).
//   Fast path: zeros are rare in uniform[0,1) input, so per 12-element row
//   chunk we take min(|v|); if nonzero the whole chunk contributes constants.
// crop: gather 256x256x3 window, loads front-batched for MLP.
// ---------------------------------------------------------------------------

#define NBATCH 32
#define SY 512
#define SX 512
#define NC 3
#define ROW_FLOATS (SX * NC)        // 1536
#define ROW_F4 (ROW_FLOATS / 4)     // 384
#define CROP 256
#define OUT_ROW_FLOATS (CROP * NC)  // 768

#define RB 32                       // rows per reduce block
#define RBLOCKS_PER_BATCH (SY / RB) // 16

#define CR 8                        // rows per crop block
#define CBLOCKS_PER_BATCH (CROP / CR) // 32

__device__ int  g_cnt[NBATCH];   // zero at load; returned to 0 every run
__device__ int  g_sx[NBATCH];
__device__ int  g_sy[NBATCH];
__device__ int  g_tick[NBATCH];
__device__ int2 g_HW[NBATCH];    // (H, W) crop origin per batch

__global__ __launch_bounds__(128) void reduce_kernel(const float* __restrict__ in) {
    const int t  = threadIdx.x;             // 0..127
    const int b  = blockIdx.y;              // 0..31
    const int y0 = blockIdx.x * RB;         // 0,32,...,480

    // Sum of x-coordinates of this thread's 12 lanes (fast-path constant).
    int xsum = 0;
    #pragma unroll
    for (int i = 0; i < 3; i++) {
        const int j = 4 * (t + i * 128);
        #pragma unroll
        for (int k = 0; k < 4; k++)
            xsum += (j + k) / 3;
    }

    const float4* __restrict__ base =
        (const float4*)(in + ((size_t)b * SY + y0) * ROW_FLOATS);

    int cnt = 0, sx = 0, sy = 0;
    #pragma unroll 4
    for (int r = 0; r < RB; r++) {
        const float4* __restrict__ row = base + (size_t)r * ROW_F4;
        const float4 a = row[t];
        const float4 c = row[t + 128];
        const float4 d = row[t + 256];

        // min(|v|) over the 12 values; == 0 iff any element is +/-0.
        const float m =
            fminf(fminf(fminf(fminf(fabsf(a.x), fabsf(a.y)),
                              fminf(fabsf(a.z), fabsf(a.w))),
                        fminf(fminf(fabsf(c.x), fabsf(c.y)),
                              fminf(fabsf(c.z), fabsf(c.w)))),
                  fminf(fminf(fabsf(d.x), fabsf(d.y)),
                        fminf(fabsf(d.z), fabsf(d.w))));

        int rc;
        if (m != 0.0f) {                    // common case: all 12 nonzero
            rc = 12;
            sx += xsum;
        } else {                            // rare: exact per-element path
            rc = 0;
            const float4 vv[3] = {a, c, d};
            #pragma unroll
            for (int i = 0; i < 3; i++) {
                const int j = 4 * (t + i * 128);
                const float e[4] = {vv[i].x, vv[i].y, vv[i].z, vv[i].w};
                #pragma unroll
                for (int k = 0; k < 4; k++)
                    if (e[k] != 0.0f) { rc++; sx += (j + k) / 3; }
            }
        }
        cnt += rc;
        sy  += (y0 + r) * rc;
    }

    // warp reduce
    #pragma unroll
    for (int o = 16; o > 0; o >>= 1) {
        cnt += __shfl_down_sync(0xFFFFFFFFu, cnt, o);
        sx  += __shfl_down_sync(0xFFFFFFFFu, sx,  o);
        sy  += __shfl_down_sync(0xFFFFFFFFu, sy,  o);
    }

    __shared__ int s_cnt, s_sx, s_sy;
    if (t == 0) { s_cnt = 0; s_sx = 0; s_sy = 0; }
    __syncthreads();
    if ((t & 31) == 0) {
        atomicAdd(&s_cnt, cnt);
        atomicAdd(&s_sx,  sx);
        atomicAdd(&s_sy,  sy);
    }
    __syncthreads();

    if (t == 0) {
        atomicAdd(&g_cnt[b], s_cnt);
        atomicAdd(&g_sx[b],  s_sx);
        atomicAdd(&g_sy[b],  s_sy);
        __threadfence();
        if (atomicAdd(&g_tick[b], 1) == RBLOCKS_PER_BATCH - 1) {
            // Last block for this batch: read+reset (scratch back to 0 for
            // the next graph replay), publish crop origin.
            const int c  = atomicExch(&g_cnt[b], 0);
            const int xs = atomicExch(&g_sx[b],  0);
            const int ys = atomicExch(&g_sy[b],  0);
            atomicExch(&g_tick[b], 0);
            // Reference numerics: int32->f32 RN, IEEE f32 divide, trunc cast.
            const float fc = __int2float_rn(c);
            const int xcm = (int)__fdiv_rn(__int2float_rn(xs), fc);
            const int ycm = (int)__fdiv_rn(__int2float_rn(ys), fc);
            int2 hw;
            hw.x = min(max(ycm - CROP / 2, 0), SY - 1 - CROP);  // H
            hw.y = min(max(xcm - CROP / 2, 0), SX - 1 - CROP);  // W
            g_HW[b] = hw;
        }
    }
}

// 192 threads, 8 output rows per block. All 32 scalar loads issued before any
// store (v[] array) so the memory system sees deep MLP. Source is only
// 4B-aligned (W*3 arbitrary); dest row is 16B-aligned -> float4 stores.
__global__ __launch_bounds__(192, 1) void crop_kernel(const float* __restrict__ in,
                                                      float* __restrict__ out) {
    const int t  = threadIdx.x;          // 0..191
    const int b  = blockIdx.y;           // batch
    const int r0 = blockIdx.x * CR;      // first output row of this block

    const int2 hw = g_HW[b];             // (H, W)

    const float* __restrict__ srcb =
        in + (size_t)b * (SY * SX * NC)
           + ((size_t)(hw.x + r0) * SX + hw.y) * NC
           + 4 * t;
    float4* __restrict__ dstb =
        (float4*)(out + ((size_t)b * CROP + r0) * OUT_ROW_FLOATS) + t;

    float4 v[CR];
    #pragma unroll
    for (int r = 0; r < CR; r++) {
        const float* __restrict__ src = srcb + (size_t)r * ROW_FLOATS;
        v[r].x = src[0];
        v[r].y = src[1];
        v[r].z = src[2];
        v[r].w = src[3];
    }
    #pragma unroll
    for (int r = 0; r < CR; r++)
        dstb[(size_t)r * (OUT_ROW_FLOATS / 4)] = v[r];
}

extern "C" void kernel_launch(void* const* d_in, const int* in_sizes, int n_in,
                              void* d_out, int out_size) {
    const float* in = (const float*)d_in[0];
    float* out = (float*)d_out;

    reduce_kernel<<<dim3(RBLOCKS_PER_BATCH, NBATCH), 128>>>(in);
    crop_kernel<<<dim3(CBLOCKS_PER_BATCH, NBATCH), 192>>>(in, out);
}

// round 6
// speedup vs baseline: 1.0547x; 1.0547x over previous
#include <cuda_runtime.h>

// ---------------------------------------------------------------------------
// TrackCrop: input [32, 512, 512, 3] f32.
// reduce: nonzero count + x/y weighted sums per batch -> centroid -> crop
// origin (published in g_HW, scratch self-resetting for graph replay).
//   Packed accumulator: acc += nz ? (x + 1<<20) : 0 -> one predicated IADD
//   per element carries both sx (low 20 bits) and cnt (high bits).
// crop: gather 256x256x3 window with fully coalesced strided scalar access
//   (warp-contiguous 128B per instruction on both load and store sides).
// ---------------------------------------------------------------------------

#define NBATCH 32
#define SY 512
#define SX 512
#define NC 3
#define ROW_FLOATS (SX * NC)        // 1536
#define ROW_F4 (ROW_FLOATS / 4)     // 384
#define CROP 256
#define OUT_ROW_FLOATS (CROP * NC)  // 768

#define RB 32                       // rows per reduce block
#define RBLOCKS_PER_BATCH (SY / RB) // 16

#define CR 8                        // rows per crop block
#define CBLOCKS_PER_BATCH (CROP / CR) // 32

#define CNT_ONE (1 << 20)           // cnt lives above bit 20; sx below
#define SX_MASK (CNT_ONE - 1)

__device__ int  g_cnt[NBATCH];   // zero at load; returned to 0 every run
__device__ int  g_sx[NBATCH];
__device__ int  g_sy[NBATCH];
__device__ int  g_tick[NBATCH];
__device__ int2 g_HW[NBATCH];    // (H, W) crop origin per batch

__global__ __launch_bounds__(128) void reduce_kernel(const float* __restrict__ in) {
    const int t  = threadIdx.x;             // 0..127
    const int b  = blockIdx.y;              // 0..31
    const int y0 = blockIdx.x * RB;         // 0,32,...,480

    // Per-lane packed weights: x-coordinate + CNT_ONE, hoisted out of the loop.
    int w[12];
    #pragma unroll
    for (int i = 0; i < 3; i++) {
        const int j = 4 * (t + i * 128);    // float index within row
        #pragma unroll
        for (int k = 0; k < 4; k++)
            w[i * 4 + k] = (j + k) / 3 + CNT_ONE;
    }

    const float4* __restrict__ base =
        (const float4*)(in + ((size_t)b * SY + y0) * ROW_FLOATS);

    int accT = 0;   // packed: sx in [0,20), cnt in [20,31)
    int sy   = 0;
    #pragma unroll 4
    for (int r = 0; r < RB; r++) {
        const float4* __restrict__ row = base + (size_t)r * ROW_F4;
        const float4 a = row[t];
        const float4 c = row[t + 128];
        const float4 d = row[t + 256];

        int acc = 0;
        if (a.x != 0.0f) acc += w[0];
        if (a.y != 0.0f) acc += w[1];
        if (a.z != 0.0f) acc += w[2];
        if (a.w != 0.0f) acc += w[3];
        if (c.x != 0.0f) acc += w[4];
        if (c.y != 0.0f) acc += w[5];
        if (c.z != 0.0f) acc += w[6];
        if (c.w != 0.0f) acc += w[7];
        if (d.x != 0.0f) acc += w[8];
        if (d.y != 0.0f) acc += w[9];
        if (d.z != 0.0f) acc += w[10];
        if (d.w != 0.0f) acc += w[11];

        accT += acc;
        sy   += (y0 + r) * (acc >> 20);     // rc for this row
    }

    int cnt = accT >> 20;        // per-thread: <= 384
    int sx  = accT & SX_MASK;    // per-thread: <= 384*511 < 2^20

    // warp reduce
    #pragma unroll
    for (int o = 16; o > 0; o >>= 1) {
        cnt += __shfl_down_sync(0xFFFFFFFFu, cnt, o);
        sx  += __shfl_down_sync(0xFFFFFFFFu, sx,  o);
        sy  += __shfl_down_sync(0xFFFFFFFFu, sy,  o);
    }

    __shared__ int s_cnt, s_sx, s_sy;
    if (t == 0) { s_cnt = 0; s_sx = 0; s_sy = 0; }
    __syncthreads();
    if ((t & 31) == 0) {
        atomicAdd(&s_cnt, cnt);
        atomicAdd(&s_sx,  sx);
        atomicAdd(&s_sy,  sy);
    }
    __syncthreads();

    if (t == 0) {
        atomicAdd(&g_cnt[b], s_cnt);
        atomicAdd(&g_sx[b],  s_sx);
        atomicAdd(&g_sy[b],  s_sy);
        __threadfence();
        if (atomicAdd(&g_tick[b], 1) == RBLOCKS_PER_BATCH - 1) {
            // Last block for this batch: read+reset (scratch back to 0 for
            // the next graph replay), publish crop origin.
            const int c  = atomicExch(&g_cnt[b], 0);
            const int xs = atomicExch(&g_sx[b],  0);
            const int ys = atomicExch(&g_sy[b],  0);
            atomicExch(&g_tick[b], 0);
            // Reference numerics: int32->f32 RN, IEEE f32 divide, trunc cast.
            const float fc = __int2float_rn(c);
            const int xcm = (int)__fdiv_rn(__int2float_rn(xs), fc);
            const int ycm = (int)__fdiv_rn(__int2float_rn(ys), fc);
            int2 hw;
            hw.x = min(max(ycm - CROP / 2, 0), SY - 1 - CROP);  // H
            hw.y = min(max(xcm - CROP / 2, 0), SX - 1 - CROP);  // W
            g_HW[b] = hw;
        }
    }
}

// 192 threads, 8 output rows per block. Thread t handles row elements
// t, t+192, t+384, t+576: every warp load/store instruction covers a
// contiguous 128B span (4 sectors) on both src and dst.
__global__ __launch_bounds__(192, 1) void crop_kernel(const float* __restrict__ in,
                                                      float* __restrict__ out) {
    const int t  = threadIdx.x;          // 0..191
    const int b  = blockIdx.y;           // batch
    const int r0 = blockIdx.x * CR;      // first output row of this block

    const int2 hw = g_HW[b];             // (H, W)

    const float* __restrict__ srcb =
        in + (size_t)b * (SY * SX * NC)
           + ((size_t)(hw.x + r0) * SX + hw.y) * NC + t;
    float* __restrict__ dstb =
        out + ((size_t)b * CROP + r0) * OUT_ROW_FLOATS + t;

    float v[CR][4];
    #pragma unroll
    for (int r = 0; r < CR; r++) {
        const float* __restrict__ src = srcb + (size_t)r * ROW_FLOATS;
        #pragma unroll
        for (int k = 0; k < 4; k++)
            v[r][k] = src[k * 192];
    }
    #pragma unroll
    for (int r = 0; r < CR; r++) {
        float* __restrict__ dst = dstb + (size_t)r * OUT_ROW_FLOATS;
        #pragma unroll
        for (int k = 0; k < 4; k++)
            dst[k * 192] = v[r][k];
    }
}

extern "C" void kernel_launch(void* const* d_in, const int* in_sizes, int n_in,
                              void* d_out, int out_size) {
    const float* in = (const float*)d_in[0];
    float* out = (float*)d_out;

    reduce_kernel<<<dim3(RBLOCKS_PER_BATCH, NBATCH), 128>>>(in);
    crop_kernel<<<dim3(CBLOCKS_PER_BATCH, NBATCH), 192>>>(in, out);
}